// round 3
// baseline (speedup 1.0000x reference)
#include <cuda_runtime.h>
#include <math.h>

#define BB 32
#define NN 1024
#define TB 256                  // pairwise tile width
#define NTB (NN/TB)             // 4 blocks per row
#define NTRI 10                 // triangle tiles over 4x4
#define PW_BLOCKS (BB*NTRI)     // 320
#define TOT_BLOCKS (PW_BLOCKS+BB)

__device__ float    g_part[BB*NTB*NN];  // S partials: [row][slot][elem]
__device__ float    g_tt[BB], g_t5[BB], g_lw[BB], g_np[BB];
__device__ float    g_row[BB];
__device__ unsigned g_cnt = 0;

__constant__ int c_ti[NTRI] = {0,0,0,0,1,1,1,2,2,3};
__constant__ int c_tj[NTRI] = {0,1,2,3,1,2,3,2,3,3};

__device__ __forceinline__ float tanh_ap(float x){
    float y; asm("tanh.approx.f32 %0, %1;" : "=f"(y) : "f"(x)); return y;
}

// ---------------------------------------------------------------------------
struct SmemRow { float s[NN]; float red[4]; };
struct SmemPw  { float2 ptj[TB]; float sjw[4][TB]; };
union  Smem    { SmemRow row; SmemPw pw; };

// block reductions for 128 threads (4 warps)
__device__ __forceinline__ float bsum128(float v, float* red, int t){
    #pragma unroll
    for (int o = 16; o; o >>= 1) v += __shfl_down_sync(0xffffffffu, v, o);
    if ((t & 31) == 0) red[t >> 5] = v;
    __syncthreads();
    if (t == 0) red[0] = red[0] + red[1] + red[2] + red[3];
    __syncthreads();
    v = red[0];
    __syncthreads();
    return v;
}
__device__ __forceinline__ float bmax128(float v, float* red, int t){
    #pragma unroll
    for (int o = 16; o; o >>= 1) v = fmaxf(v, __shfl_down_sync(0xffffffffu, v, o));
    if ((t & 31) == 0) red[t >> 5] = v;
    __syncthreads();
    if (t == 0) red[0] = fmaxf(fmaxf(red[0], red[1]), fmaxf(red[2], red[3]));
    __syncthreads();
    v = red[0];
    __syncthreads();
    return v;
}

// ---------------------------------------------------------------------------
// K1: blocks [0,320): pairwise S-partials (weight-free)
//     blocks [320,352): per-row sort + thresholds + tie stats + listwise
// ---------------------------------------------------------------------------
__global__ void __launch_bounds__(128, 8)
k1(const float* __restrict__ yp, const float* __restrict__ yt){
    __shared__ Smem sm;
    const int t = threadIdx.x, w = t >> 5, l = t & 31;

    if (blockIdx.x < PW_BLOCKS){
        // ----------------- pairwise tile -----------------
        const int row  = blockIdx.x / NTRI;
        const int tile = blockIdx.x % NTRI;
        const int I = c_ti[tile], J = c_tj[tile];
        const float* pr = yp + row * NN;
        const float* tr = yt + row * NN;

        #pragma unroll
        for (int m = 0; m < 2; m++){
            int e = t + m * 128;
            sm.pw.ptj[e] = make_float2(pr[J*TB + e] * 0.5f, tr[J*TB + e]);
        }
        #pragma unroll
        for (int m = 0; m < 8; m++) sm.pw.sjw[w][l + m*32] = 0.f;
        __syncthreads();

        const int   i1  = I*TB + t, i2 = i1 + 128;
        const float ph1 = pr[i1] * 0.5f, tv1 = tr[i1];
        const float ph2 = pr[i2] * 0.5f, tv2 = tr[i2];
        float acc1 = 0.f, acc2 = 0.f;
        float* sj = sm.pw.sjw[w];

        if (I != J){
            #pragma unroll 4
            for (int k = 0; k < TB; k++){
                int j = (t + k) & (TB - 1);
                float2 c = sm.pw.ptj[j];
                float d1 = ph1 - c.x;
                float x1 = (tv1 > c.y) ? -d1 : d1;
                float s1 = fmaf(0.5f, tanh_ap(x1), 0.5f);
                float c1 = (tv1 != c.y) ? s1 : 0.f;
                float d2 = ph2 - c.x;
                float x2 = (tv2 > c.y) ? -d2 : d2;
                float s2 = fmaf(0.5f, tanh_ap(x2), 0.5f);
                float c2 = (tv2 != c.y) ? s2 : 0.f;
                acc1 += c1; acc2 += c2;
                sj[j] += c1 + c2;
            }
        } else {
            #pragma unroll 4
            for (int k = 0; k < TB; k++){
                int j = (t + k) & (TB - 1);
                float2 c = sm.pw.ptj[j];
                float d1 = ph1 - c.x;
                float x1 = (tv1 > c.y) ? -d1 : d1;
                float s1 = fmaf(0.5f, tanh_ap(x1), 0.5f);
                float c1 = (j > t       && tv1 != c.y) ? s1 : 0.f;
                float d2 = ph2 - c.x;
                float x2 = (tv2 > c.y) ? -d2 : d2;
                float s2 = fmaf(0.5f, tanh_ap(x2), 0.5f);
                float c2 = (j > t + 128 && tv2 != c.y) ? s2 : 0.f;
                acc1 += c1; acc2 += c2;
                sj[j] += c1 + c2;
            }
        }
        __syncthreads();

        #pragma unroll
        for (int m = 0; m < 2; m++){
            int e = t + m * 128;
            float sjt = sm.pw.sjw[0][e] + sm.pw.sjw[1][e]
                      + sm.pw.sjw[2][e] + sm.pw.sjw[3][e];
            float acc = m ? acc2 : acc1;
            if (I == J){
                g_part[(row*NTB + I)*NN + I*TB + e] = acc + sjt;
            } else {
                g_part[(row*NTB + J)*NN + I*TB + e] = acc;   // i-side, slot J
                g_part[(row*NTB + I)*NN + J*TB + e] = sjt;   // j-side, slot I
            }
        }
    } else {
        // ----------------- per-row stats -----------------
        const int row = blockIdx.x - PW_BLOCKS;
        const float* pr = yp + row * NN;
        const float* tr = yt + row * NN;
        float* s   = sm.row.s;
        float* red = sm.row.red;

        #pragma unroll
        for (int m = 0; m < 8; m++) s[t + m*128] = tr[t + m*128];
        __syncthreads();

        // bitonic sort, 8 elements per thread
        for (int k = 2; k <= NN; k <<= 1){
            for (int j = k >> 1; j > 0; j >>= 1){
                #pragma unroll
                for (int m = 0; m < 8; m++){
                    int idx = t + m*128, p = idx ^ j;
                    if (p > idx){
                        float a = s[idx], b = s[p];
                        bool up = (idx & k) == 0;
                        if ((a > b) == up){ s[idx] = b; s[p] = a; }
                    }
                }
                __syncthreads();
            }
        }

        const float tt = s[972];     // tail mask == y >= interp-quantile
        const float t5 = s[NN - 5];  // top-5 mask
        const float mt = s[NN - 1];  // row max of y_true

        // tie-run stats (T2 = sum L(L-1) over equal-value runs)
        float tie = 0.f;
        #pragma unroll
        for (int m = 0; m < 8; m++){
            int idx = t + m*128;
            float sv = s[idx];
            int d = 0, k2 = idx + 1;
            while (k2 < NN && s[k2] == sv){ ++d; ++k2; }
            tie += 2.f * (float)d;
        }

        float pv[8], tvv[8];
        #pragma unroll
        for (int m = 0; m < 8; m++){ pv[m] = pr[t + m*128]; tvv[m] = tr[t + m*128]; }

        float mp = -3.4e38f;
        #pragma unroll
        for (int m = 0; m < 8; m++) mp = fmaxf(mp, pv[m]);
        mp = bmax128(mp, red, t);

        float spl = 0.f, stl = 0.f;
        #pragma unroll
        for (int m = 0; m < 8; m++){
            spl += __expf(pv[m]  - mp);
            stl += __expf(tvv[m] - mt);
        }
        const float sp = bsum128(spl, red, t);
        const float st = bsum128(stl, red, t);
        const float rsp = 1.0f / sp, rst = 1.0f / st;

        float numl = 0.f, denl = 0.f;
        #pragma unroll
        for (int m = 0; m < 8; m++){
            float tv2 = tvv[m];
            float wv = ((tv2 >= tt) ? 10.f : 1.f) * ((tv2 >= t5) ? 2.f : 1.f);
            float pp = __expf(pv[m] - mp) * rsp;
            float tp = __expf(tv2   - mt) * rst;
            numl += tp * logf(pp + 1e-12f) * wv;
            denl += wv;
        }
        const float num = bsum128(numl, red, t);
        const float den = bsum128(denl, red, t);
        const float T2  = bsum128(tie,  red, t);

        if (t == 0){
            g_tt[row] = tt;
            g_t5[row] = t5;
            g_lw[row] = -num / (den + 1e-12f);
            float np = (float)NN * (float)(NN - 1) - T2;
            if (np < 1.f) np = 1.f;
            g_np[row] = np;
        }
    }
}

// ---------------------------------------------------------------------------
// K2: combine — per row: pairwise = 2*sum(w_e*S_e)/np; + listwise; final mean
// ---------------------------------------------------------------------------
__global__ void __launch_bounds__(256, 4)
k2(const float* __restrict__ yt, float* __restrict__ out){
    const int row = blockIdx.x, t = threadIdx.x;
    __shared__ float red[8];
    __shared__ int last_flag;

    const float tt = g_tt[row], t5 = g_t5[row];
    const float* tr = yt + row * NN;

    float acc = 0.f;
    #pragma unroll
    for (int m = 0; m < 4; m++){
        int e = t + m * 256;
        float S = g_part[(row*NTB + 0)*NN + e] + g_part[(row*NTB + 1)*NN + e]
                + g_part[(row*NTB + 2)*NN + e] + g_part[(row*NTB + 3)*NN + e];
        float tv = tr[e];
        float wv = ((tv >= tt) ? 10.f : 1.f) * ((tv >= t5) ? 2.f : 1.f);
        acc += wv * S;
    }
    #pragma unroll
    for (int o = 16; o; o >>= 1) acc += __shfl_down_sync(0xffffffffu, acc, o);
    if ((t & 31) == 0) red[t >> 5] = acc;
    __syncthreads();

    if (t == 0){
        float tot = 0.f;
        #pragma unroll
        for (int i = 0; i < 8; i++) tot += red[i];
        g_row[row] = g_lw[row] + 2.f * tot / g_np[row];
        __threadfence();
        last_flag = (atomicAdd(&g_cnt, 1u) == BB - 1);
    }
    __syncthreads();

    if (last_flag && t < 32){
        __threadfence();
        float v = ((volatile float*)g_row)[t];
        #pragma unroll
        for (int o = 16; o; o >>= 1) v += __shfl_down_sync(0xffffffffu, v, o);
        if (t == 0){
            out[0] = v * (1.0f / (float)BB);
            g_cnt = 0;   // restore for next graph replay
        }
    }
}

// ---------------------------------------------------------------------------
extern "C" void kernel_launch(void* const* d_in, const int* in_sizes, int n_in,
                              void* d_out, int out_size){
    const float* yp = (const float*)d_in[0];   // y_pred [32,1024]
    const float* yt = (const float*)d_in[1];   // y_true [32,1024]
    k1<<<TOT_BLOCKS, 128>>>(yp, yt);
    k2<<<BB, 256>>>(yt, (float*)d_out);
}